// round 11
// baseline (speedup 1.0000x reference)
#include <cuda_runtime.h>
#include <cuda_fp16.h>
#include <cstdint>

#define B_  2
#define S_  4096
#define E_  768
#define H_  12
#define D_  64
#define P_  16
#define SK_ 4112   // P + S

// -------- scratch (static device globals; no allocation) --------
__device__ float g_Q[B_*H_*S_*D_];    // [b][h][s][d], scale*log2e folded in
__device__ float g_K[B_*H_*SK_*D_];
__device__ float g_V[B_*H_*SK_*D_];
__device__ float g_ctx[B_*S_*E_];

// ================= helpers =================
__device__ __forceinline__ uint32_t f2h2(float x, float y){
    __half2 h = __floats2half2_rn(x, y);
    return *(uint32_t*)&h;
}
__device__ __forceinline__ uint32_t cvt_tf32(float x){
    uint32_t r; asm("cvt.rna.tf32.f32 %0, %1;" : "=r"(r) : "f"(x)); return r;
}

// mma.sync m16n8k16 fp16 in / fp32 accum (sm_80+ PTX; proven in rounds 7/9)
__device__ __forceinline__ void mma16(float* c, const uint32_t* a, const uint32_t* b){
    asm volatile(
        "mma.sync.aligned.m16n8k16.row.col.f32.f16.f16.f32 "
        "{%0,%1,%2,%3}, {%4,%5,%6,%7}, {%8,%9}, {%0,%1,%2,%3};"
        : "+f"(c[0]), "+f"(c[1]), "+f"(c[2]), "+f"(c[3])
        : "r"(a[0]), "r"(a[1]), "r"(a[2]), "r"(a[3]), "r"(b[0]), "r"(b[1]));
}
// mma.sync m16n8k8 tf32 (proven in rounds 4/7/9)
__device__ __forceinline__ void mma8(float* c, const uint32_t* a, const uint32_t* b){
    asm volatile(
        "mma.sync.aligned.m16n8k8.row.col.f32.tf32.tf32.f32 "
        "{%0,%1,%2,%3}, {%4,%5,%6,%7}, {%8,%9}, {%0,%1,%2,%3};"
        : "+f"(c[0]), "+f"(c[1]), "+f"(c[2]), "+f"(c[3])
        : "r"(a[0]), "r"(a[1]), "r"(a[2]), "r"(a[3]), "r"(b[0]), "r"(b[1]));
}

// fast exp2 on FMA pipe (avoids MUFU bottleneck)
__device__ __forceinline__ float exp2_fast(float x) {
    x = fmaxf(x, -126.0f);
    float t = rintf(x);
    float f = x - t;
    float p = 1.3333558e-3f;
    p = fmaf(p, f, 9.6181292e-3f);
    p = fmaf(p, f, 5.5504109e-2f);
    p = fmaf(p, f, 2.4022651e-1f);
    p = fmaf(p, f, 6.9314718e-1f);
    p = fmaf(p, f, 1.0f);
    return __int_as_float(__float_as_int(p) + ((int)t << 23));
}

// ================= fp16 GEMM: out = X@W^T + b, M=8192, N=K=768 ============
// CTA 128x128, 512 threads, 16 warps 8m x 2n (warp tile 16x64).
// K chunks of 32, double-buffered, register staging. 16 warps/SM doubles
// latency hiding vs the 256-thread round-9 version (occ was the bottleneck).
// smem half2-words: A0@0, B0@2560, A1@5120, B1@7680; row stride 20 (16+4 pad).
#define GST 20
#define GEMM_SMEM (10240u * 4u)

template<int MODE>
__global__ void __launch_bounds__(512, 1) gemm_mma(
    const float* __restrict__ X, const float* __restrict__ W,
    const float* __restrict__ bias, float* __restrict__ out,
    float scale, int seq_off, int seq_tot)
{
    extern __shared__ uint32_t sm4[];
    const int tid  = threadIdx.x;
    const int lane = tid & 31, warp = tid >> 5;
    const int gid  = lane >> 2, tg = lane & 3;
    const int wx   = warp & 1,  wy = warp >> 1;   // wy 0..7 (m), wx 0..1 (n)
    const int m0 = blockIdx.y * 128, n0 = blockIdx.x * 128;

    float4 ra[2], rb[2];

    // preload chunk 0
    #pragma unroll
    for (int it = 0; it < 2; ++it) {
        const int i = tid + it * 512, row = i >> 3, c4 = i & 7;
        ra[it] = *(const float4*)(X + (size_t)(m0 + row) * E_ + c4 * 4);
        rb[it] = *(const float4*)(W + (size_t)(n0 + row) * E_ + c4 * 4);
    }

    float c[8][4] = {};

    for (int ch = 0; ch < 24; ++ch) {
        // store staged regs into buffer ch&1 (packed half2)
        {
            uint32_t* A  = sm4 + (ch & 1) * 5120;
            uint32_t* Bv = A + 2560;
            #pragma unroll
            for (int it = 0; it < 2; ++it) {
                const int i = tid + it * 512, row = i >> 3, c4 = i & 7;
                *(uint2*)(A  + row * GST + c4 * 2) =
                    make_uint2(f2h2(ra[it].x, ra[it].y), f2h2(ra[it].z, ra[it].w));
                *(uint2*)(Bv + row * GST + c4 * 2) =
                    make_uint2(f2h2(rb[it].x, rb[it].y), f2h2(rb[it].z, rb[it].w));
            }
        }
        __syncthreads();
        // stage next chunk (global loads only; no smem hazard)
        if (ch < 23) {
            #pragma unroll
            for (int it = 0; it < 2; ++it) {
                const int i = tid + it * 512, row = i >> 3, c4 = i & 7;
                ra[it] = *(const float4*)(X + (size_t)(m0 + row) * E_ + (ch + 1) * 32 + c4 * 4);
                rb[it] = *(const float4*)(W + (size_t)(n0 + row) * E_ + (ch + 1) * 32 + c4 * 4);
            }
        }
        // MMA on buffer ch&1: 2 k16 steps, warp tile 16x64
        const uint32_t* A  = sm4 + (ch & 1) * 5120;
        const uint32_t* Bv = A + 2560;
        #pragma unroll
        for (int s = 0; s < 2; ++s) {
            const int ko = s * 8;
            uint32_t a[4], b[8][2];
            const int r = wy * 16 + gid;
            a[0] = A[r * GST + ko + tg];
            a[1] = A[(r + 8) * GST + ko + tg];
            a[2] = A[r * GST + ko + tg + 4];
            a[3] = A[(r + 8) * GST + ko + tg + 4];
            #pragma unroll
            for (int nf = 0; nf < 8; ++nf) {
                const int col = wx * 64 + nf * 8 + gid;
                b[nf][0] = Bv[col * GST + ko + tg];
                b[nf][1] = Bv[col * GST + ko + tg + 4];
            }
            #pragma unroll
            for (int nf = 0; nf < 8; ++nf)
                mma16(c[nf], a, b[nf]);
        }
    }

    // epilogue: bias + scale
    #pragma unroll
    for (int h2 = 0; h2 < 2; ++h2) {
        const int row = m0 + wy * 16 + gid + h2 * 8;
        #pragma unroll
        for (int nf = 0; nf < 8; ++nf) {
            const int col = n0 + wx * 64 + nf * 8 + 2 * tg;
            float2 o;
            o.x = (c[nf][h2 * 2 + 0] + bias[col])     * scale;
            o.y = (c[nf][h2 * 2 + 1] + bias[col + 1]) * scale;
            if (MODE == 0) {
                *(float2*)&out[(size_t)row * E_ + col] = o;
            } else {
                const int b = row >> 12, s = row & (S_ - 1);
                const int h = col >> 6, d0 = col & 63;
                *(float2*)&out[((size_t)(b * H_ + h) * seq_tot + seq_off + s) * D_ + d0] = o;
            }
        }
    }
}

// -------- prompt prefix scatter (idempotent; launched twice to steer ncu) ---
__global__ void prompt_copy(const float* __restrict__ pr) {
    int idx = blockIdx.x * 256 + threadIdx.x;
    if (idx >= B_*2*P_*H_*D_) return;
    int t = idx;
    const int d = t & 63;  t >>= 6;
    const int h = t % H_;  t /= H_;
    const int p = t & 15;  t >>= 4;
    const int c = t & 1;   t >>= 1;
    const int b = t;
    const float v = pr[idx];
    const int dst = ((b*H_ + h) * SK_ + p) * D_ + d;
    if (c == 0) g_K[dst] = v; else g_V[dst] = v;
}

// ============ hybrid attention: fp16 QK^T + tf32 PV (m=0 softmax) ==========
// CTA: 128 q rows x one (b,h), 512 threads, 16 warps 4q x 4k
// (warp tile 32q x 16k for QK; 32q x 16d for PV).
// Same instruction set / layouts as the round-9 passing kernel; only the
// warp partition changed to double resident warps per SM.
// Software-pipelined K/V prefetch. O in registers across all 65 K-tiles
// (m=0 base-2 softmax); divide by total sum at end.
// smem words:
//   Qs @0      fp16 [128][36]  (half2 words)          4608 w
//   Ks @4608   fp16 [64][36]                          2304 w
//   Vt @6912   tf32 [64 d][68 k]                      4352 w
//   Ps @11264  tf32 [128][68]                         8704 w
//   Ls @19968  float [4][128]                          512 w   total 20480 w
#define QST 36
#define VST 68
#define ATTN_SMEM (20480u * 4u)

__global__ void __launch_bounds__(512, 1) attn_mma(
    const float* __restrict__ Qg, const float* __restrict__ Kg,
    const float* __restrict__ Vg, float* __restrict__ ctx)
{
    extern __shared__ uint32_t sm4[];
    uint32_t* Qs = sm4;
    uint32_t* Ks = sm4 + 4608;
    uint32_t* Vt = sm4 + 6912;
    uint32_t* Ps = sm4 + 11264;
    float*    Ls = (float*)(sm4 + 19968);

    const int tid  = threadIdx.x;
    const int lane = tid & 31, warp = tid >> 5;
    const int gid  = lane >> 2, tg = lane & 3;
    const int wk   = warp & 3,  wq = warp >> 2;   // wq 0..3 (q), wk 0..3 (k / d)

    const int b = blockIdx.z, h = blockIdx.y;
    const int q0 = blockIdx.x * 128;
    const float* qg = Qg + ((size_t)(b*H_ + h) * S_ + q0) * D_;
    const float* kg = Kg + (size_t)(b*H_ + h) * SK_ * D_;
    const float* vg = Vg + (size_t)(b*H_ + h) * SK_ * D_;

    // load Q tile (scale*log2e already folded in projection), fp16 packed
    #pragma unroll
    for (int it = 0; it < 4; ++it) {
        const int i = tid + it * 512, row = i >> 4, c4 = i & 15;
        const float4 a = *(const float4*)(qg + (size_t)row * D_ + c4 * 4);
        *(uint2*)(Qs + row * QST + c4 * 2) =
            make_uint2(f2h2(a.x, a.y), f2h2(a.z, a.w));
    }

    float o[2][2][4] = {};      // [mf][nf][4]
    float lacc[2][2] = {};      // [mf][h2]
    float4 rk[2], rv[2];

    // preload tile j=0 into registers
    #pragma unroll
    for (int it = 0; it < 2; ++it) {
        const int i = tid + it * 512, row = i >> 4, c4 = i & 15;
        rk[it] = *(const float4*)(kg + (size_t)row * D_ + c4 * 4);
        rv[it] = *(const float4*)(vg + (size_t)row * D_ + c4 * 4);
    }

    for (int j = 0; j < 65; ++j) {
        __syncthreads();   // (A) prior iteration's smem reads complete
        // store staged tile j into smem (K fp16 [k][d]; V tf32 transposed [d][k])
        #pragma unroll
        for (int it = 0; it < 2; ++it) {
            const int i = tid + it * 512, row = i >> 4, c4 = i & 15;
            *(uint2*)(Ks + row * QST + c4 * 2) =
                make_uint2(f2h2(rk[it].x, rk[it].y), f2h2(rk[it].z, rk[it].w));
            const int d0 = c4 * 4;
            Vt[(d0+0) * VST + row] = cvt_tf32(rv[it].x);
            Vt[(d0+1) * VST + row] = cvt_tf32(rv[it].y);
            Vt[(d0+2) * VST + row] = cvt_tf32(rv[it].z);
            Vt[(d0+3) * VST + row] = cvt_tf32(rv[it].w);
        }
        __syncthreads();   // (B) tiles ready

        // prefetch tile j+1 (latency hidden under QK + softmax + PV)
        if (j < 64) {
            #pragma unroll
            for (int it = 0; it < 2; ++it) {
                const int i = tid + it * 512, row = i >> 4, c4 = i & 15;
                const int kr = (j + 1) * 64 + row;
                rk[it] = make_float4(0.f, 0.f, 0.f, 0.f);
                rv[it] = rk[it];
                if (kr < SK_) {
                    rk[it] = *(const float4*)(kg + (size_t)kr * D_ + c4 * 4);
                    rv[it] = *(const float4*)(vg + (size_t)kr * D_ + c4 * 4);
                }
            }
        }

        // S = Q K^T : fp16, warp tile 32q x 16k, 4 k16 steps over d
        float c[2][2][4] = {};
        #pragma unroll
        for (int s = 0; s < 4; ++s) {
            const int ko = s * 8;
            uint32_t a[2][4], bfr[2][2];
            #pragma unroll
            for (int mf = 0; mf < 2; ++mf) {
                const int r = wq * 32 + mf * 16 + gid;
                a[mf][0] = Qs[r * QST + ko + tg];
                a[mf][1] = Qs[(r + 8) * QST + ko + tg];
                a[mf][2] = Qs[r * QST + ko + tg + 4];
                a[mf][3] = Qs[(r + 8) * QST + ko + tg + 4];
            }
            #pragma unroll
            for (int nf = 0; nf < 2; ++nf) {
                const int col = wk * 16 + nf * 8 + gid;
                bfr[nf][0] = Ks[col * QST + ko + tg];
                bfr[nf][1] = Ks[col * QST + ko + tg + 4];
            }
            #pragma unroll
            for (int mf = 0; mf < 2; ++mf)
                #pragma unroll
                for (int nf = 0; nf < 2; ++nf)
                    mma16(c[mf][nf], a[mf], bfr[nf]);
        }

        // softmax (m=0): p = exp2(s); tail tile j=64 keeps only local cols 0..15
        // (= wk 0); all wk>0 columns are past SK.
        #pragma unroll
        for (int mf = 0; mf < 2; ++mf)
            #pragma unroll
            for (int nf = 0; nf < 2; ++nf) {
                #pragma unroll
                for (int e = 0; e < 4; ++e) {
                    float p = exp2_fast(c[mf][nf][e]);
                    if (j == 64 && wk > 0) p = 0.f;
                    c[mf][nf][e] = p;
                    lacc[mf][e >> 1] += p;
                }
            }

        // store P as tf32 for tf32 PV
        #pragma unroll
        for (int mf = 0; mf < 2; ++mf)
            #pragma unroll
            for (int h2 = 0; h2 < 2; ++h2) {
                const int row = wq * 32 + mf * 16 + gid + h2 * 8;
                #pragma unroll
                for (int nf = 0; nf < 2; ++nf) {
                    const int col = wk * 16 + nf * 8 + 2 * tg;
                    uint2 v;
                    v.x = cvt_tf32(c[mf][nf][h2 * 2 + 0]);
                    v.y = cvt_tf32(c[mf][nf][h2 * 2 + 1]);
                    *(uint2*)(Ps + row * VST + col) = v;
                }
            }
        __syncthreads();   // (C) P ready

        // O += P V : tf32 m16n8k8, warp tile 32q x 16d over full k=64
        #pragma unroll
        for (int k8 = 0; k8 < 8; ++k8) {
            const int kk = k8 * 8;
            uint32_t a[2][4], bfr[2][2];
            #pragma unroll
            for (int mf = 0; mf < 2; ++mf) {
                const int r = wq * 32 + mf * 16 + gid;
                a[mf][0] = Ps[r * VST + kk + tg];
                a[mf][1] = Ps[(r + 8) * VST + kk + tg];
                a[mf][2] = Ps[r * VST + kk + tg + 4];
                a[mf][3] = Ps[(r + 8) * VST + kk + tg + 4];
            }
            #pragma unroll
            for (int nf = 0; nf < 2; ++nf) {
                const int col = wk * 16 + nf * 8 + gid;   // d index
                bfr[nf][0] = Vt[col * VST + kk + tg];
                bfr[nf][1] = Vt[col * VST + kk + tg + 4];
            }
            #pragma unroll
            for (int mf = 0; mf < 2; ++mf)
                #pragma unroll
                for (int nf = 0; nf < 2; ++nf)
                    mma8(o[mf][nf], a[mf], bfr[nf]);
        }
    }

    // reduce row sums over quad lanes (16 cols per warp), store per wk block
    #pragma unroll
    for (int mf = 0; mf < 2; ++mf)
        #pragma unroll
        for (int h2 = 0; h2 < 2; ++h2) {
            float v = lacc[mf][h2];
            v += __shfl_xor_sync(0xffffffffu, v, 1);
            v += __shfl_xor_sync(0xffffffffu, v, 2);
            if (tg == 0) {
                const int row = wq * 32 + mf * 16 + gid + h2 * 8;
                Ls[wk * 128 + row] = v;
            }
        }
    __syncthreads();

    // epilogue: O / l -> ctx
    #pragma unroll
    for (int mf = 0; mf < 2; ++mf)
        #pragma unroll
        for (int h2 = 0; h2 < 2; ++h2) {
            const int row = wq * 32 + mf * 16 + gid + h2 * 8;
            const float inv = 1.0f /
                (Ls[row] + Ls[128 + row] + Ls[256 + row] + Ls[384 + row]);
            float* dst = &ctx[((size_t)b * S_ + q0 + row) * E_ + h * 64];
            #pragma unroll
            for (int nf = 0; nf < 2; ++nf) {
                const int col = wk * 16 + nf * 8 + 2 * tg;
                float2 v;
                v.x = o[mf][nf][h2 * 2 + 0] * inv;
                v.y = o[mf][nf][h2 * 2 + 1] * inv;
                *(float2*)&dst[col] = v;
            }
        }
}

// ================= launch =================
extern "C" void kernel_launch(void* const* d_in, const int* in_sizes, int n_in,
                              void* d_out, int out_size) {
    const float* q  = (const float*)d_in[0];
    const float* k  = (const float*)d_in[1];
    const float* v  = (const float*)d_in[2];
    const float* pr = (const float*)d_in[3];
    const float* Wq = (const float*)d_in[4];
    const float* bq = (const float*)d_in[5];
    const float* Wk = (const float*)d_in[6];
    const float* bk = (const float*)d_in[7];
    const float* Wv = (const float*)d_in[8];
    const float* bv = (const float*)d_in[9];
    const float* Wo = (const float*)d_in[10];
    const float* bo = (const float*)d_in[11];
    float* out = (float*)d_out;

    void *gQ, *gK, *gV, *gctx;
    cudaGetSymbolAddress(&gQ, g_Q);
    cudaGetSymbolAddress(&gK, g_K);
    cudaGetSymbolAddress(&gV, g_V);
    cudaGetSymbolAddress(&gctx, g_ctx);

    cudaFuncSetAttribute(gemm_mma<0>, cudaFuncAttributeMaxDynamicSharedMemorySize, GEMM_SMEM);
    cudaFuncSetAttribute(gemm_mma<1>, cudaFuncAttributeMaxDynamicSharedMemorySize, GEMM_SMEM);
    cudaFuncSetAttribute(attn_mma,    cudaFuncAttributeMaxDynamicSharedMemorySize, ATTN_SMEM);

    const dim3 gg(6, 64);   // N tiles x M tiles
    const float qscale = 0.125f * 1.4426950408889634f;  // d^-0.5 * log2(e)

    // Launch order chosen so global launch index 5 (ncu -s 5 -c 1) = attn_mma.
    // prompt_copy is idempotent and commutes with the projections (disjoint rows).
    prompt_copy<<<(B_*2*P_*H_*D_ + 255)/256, 256>>>(pr);                       // 0
    gemm_mma<1><<<gg, 512, GEMM_SMEM>>>(q, Wq, bq, (float*)gQ, qscale, 0, S_); // 1
    gemm_mma<1><<<gg, 512, GEMM_SMEM>>>(k, Wk, bk, (float*)gK, 1.0f, P_, SK_); // 2
    gemm_mma<1><<<gg, 512, GEMM_SMEM>>>(v, Wv, bv, (float*)gV, 1.0f, P_, SK_); // 3
    prompt_copy<<<(B_*2*P_*H_*D_ + 255)/256, 256>>>(pr);                       // 4 (dup)
    attn_mma<<<dim3(S_/128, H_, B_), 512, ATTN_SMEM>>>(                        // 5 <- ncu
        (const float*)gQ, (const float*)gK, (const float*)gV, (float*)gctx);
    gemm_mma<0><<<gg, 512, GEMM_SMEM>>>((const float*)gctx, Wo, bo, out, 1.0f, 0, 0); // 6
}

// round 12
// speedup vs baseline: 1.1215x; 1.1215x over previous
#include <cuda_runtime.h>
#include <cuda_fp16.h>
#include <cstdint>

#define B_  2
#define S_  4096
#define E_  768
#define H_  12
#define D_  64
#define P_  16
#define SK_ 4112   // P + S

// -------- scratch (static device globals; no allocation) --------
__device__ float g_Q[B_*H_*S_*D_];    // [b][h][s][d], scale*log2e folded in
__device__ float g_K[B_*H_*SK_*D_];
__device__ float g_V[B_*H_*SK_*D_];
__device__ float g_ctx[B_*S_*E_];

// ================= helpers =================
__device__ __forceinline__ uint32_t f2h2(float x, float y){
    __half2 h = __floats2half2_rn(x, y);
    return *(uint32_t*)&h;
}
__device__ __forceinline__ uint32_t cvt_tf32(float x){
    uint32_t r; asm("cvt.rna.tf32.f32 %0, %1;" : "=r"(r) : "f"(x)); return r;
}

// mma.sync m16n8k16 fp16 in / fp32 accum (sm_80+ PTX; proven rounds 7/9/11)
__device__ __forceinline__ void mma16(float* c, const uint32_t* a, const uint32_t* b){
    asm volatile(
        "mma.sync.aligned.m16n8k16.row.col.f32.f16.f16.f32 "
        "{%0,%1,%2,%3}, {%4,%5,%6,%7}, {%8,%9}, {%0,%1,%2,%3};"
        : "+f"(c[0]), "+f"(c[1]), "+f"(c[2]), "+f"(c[3])
        : "r"(a[0]), "r"(a[1]), "r"(a[2]), "r"(a[3]), "r"(b[0]), "r"(b[1]));
}
// mma.sync m16n8k8 tf32 (proven rounds 4/7/9/11)
__device__ __forceinline__ void mma8(float* c, const uint32_t* a, const uint32_t* b){
    asm volatile(
        "mma.sync.aligned.m16n8k8.row.col.f32.tf32.tf32.f32 "
        "{%0,%1,%2,%3}, {%4,%5,%6,%7}, {%8,%9}, {%0,%1,%2,%3};"
        : "+f"(c[0]), "+f"(c[1]), "+f"(c[2]), "+f"(c[3])
        : "r"(a[0]), "r"(a[1]), "r"(a[2]), "r"(a[3]), "r"(b[0]), "r"(b[1]));
}

// fast exp2 on FMA pipe (avoids MUFU bottleneck)
__device__ __forceinline__ float exp2_fast(float x) {
    x = fmaxf(x, -126.0f);
    float t = rintf(x);
    float f = x - t;
    float p = 1.3333558e-3f;
    p = fmaf(p, f, 9.6181292e-3f);
    p = fmaf(p, f, 5.5504109e-2f);
    p = fmaf(p, f, 2.4022651e-1f);
    p = fmaf(p, f, 6.9314718e-1f);
    p = fmaf(p, f, 1.0f);
    return __int_as_float(__float_as_int(p) + ((int)t << 23));
}

// ================= fp16 GEMM: out = X@W^T + b, M=8192, N=K=768 ============
// Round-9 passing configuration, verbatim: CTA 128x128, 256 threads,
// 8 warps 4m x 2n (warp tile 32x64). K chunks of 32, double-buffered.
#define GST 20
#define GEMM_SMEM (10240u * 4u)

template<int MODE>
__global__ void __launch_bounds__(256, 1) gemm_mma(
    const float* __restrict__ X, const float* __restrict__ W,
    const float* __restrict__ bias, float* __restrict__ out,
    float scale, int seq_off, int seq_tot)
{
    extern __shared__ uint32_t sm4[];
    const int tid  = threadIdx.x;
    const int lane = tid & 31, warp = tid >> 5;
    const int gid  = lane >> 2, tg = lane & 3;
    const int wx   = warp & 1,  wy = warp >> 1;
    const int m0 = blockIdx.y * 128, n0 = blockIdx.x * 128;

    float4 ra[4], rb[4];

    #pragma unroll
    for (int it = 0; it < 4; ++it) {
        const int i = tid + it * 256, row = i >> 3, c4 = i & 7;
        ra[it] = *(const float4*)(X + (size_t)(m0 + row) * E_ + c4 * 4);
        rb[it] = *(const float4*)(W + (size_t)(n0 + row) * E_ + c4 * 4);
    }

    float c[2][8][4] = {};

    for (int ch = 0; ch < 24; ++ch) {
        {
            uint32_t* A  = sm4 + (ch & 1) * 5120;
            uint32_t* Bv = A + 2560;
            #pragma unroll
            for (int it = 0; it < 4; ++it) {
                const int i = tid + it * 256, row = i >> 3, c4 = i & 7;
                *(uint2*)(A  + row * GST + c4 * 2) =
                    make_uint2(f2h2(ra[it].x, ra[it].y), f2h2(ra[it].z, ra[it].w));
                *(uint2*)(Bv + row * GST + c4 * 2) =
                    make_uint2(f2h2(rb[it].x, rb[it].y), f2h2(rb[it].z, rb[it].w));
            }
        }
        __syncthreads();
        if (ch < 23) {
            #pragma unroll
            for (int it = 0; it < 4; ++it) {
                const int i = tid + it * 256, row = i >> 3, c4 = i & 7;
                ra[it] = *(const float4*)(X + (size_t)(m0 + row) * E_ + (ch + 1) * 32 + c4 * 4);
                rb[it] = *(const float4*)(W + (size_t)(n0 + row) * E_ + (ch + 1) * 32 + c4 * 4);
            }
        }
        const uint32_t* A  = sm4 + (ch & 1) * 5120;
        const uint32_t* Bv = A + 2560;
        #pragma unroll
        for (int s = 0; s < 2; ++s) {
            const int ko = s * 8;
            uint32_t a[2][4], b[8][2];
            #pragma unroll
            for (int mf = 0; mf < 2; ++mf) {
                const int r = wy * 32 + mf * 16 + gid;
                a[mf][0] = A[r * GST + ko + tg];
                a[mf][1] = A[(r + 8) * GST + ko + tg];
                a[mf][2] = A[r * GST + ko + tg + 4];
                a[mf][3] = A[(r + 8) * GST + ko + tg + 4];
            }
            #pragma unroll
            for (int nf = 0; nf < 8; ++nf) {
                const int col = wx * 64 + nf * 8 + gid;
                b[nf][0] = Bv[col * GST + ko + tg];
                b[nf][1] = Bv[col * GST + ko + tg + 4];
            }
            #pragma unroll
            for (int mf = 0; mf < 2; ++mf)
                #pragma unroll
                for (int nf = 0; nf < 8; ++nf)
                    mma16(c[mf][nf], a[mf], b[nf]);
        }
    }

    #pragma unroll
    for (int mf = 0; mf < 2; ++mf)
        #pragma unroll
        for (int h2 = 0; h2 < 2; ++h2) {
            const int row = m0 + wy * 32 + mf * 16 + gid + h2 * 8;
            #pragma unroll
            for (int nf = 0; nf < 8; ++nf) {
                const int col = n0 + wx * 64 + nf * 8 + 2 * tg;
                float2 o;
                o.x = (c[mf][nf][h2 * 2 + 0] + bias[col])     * scale;
                o.y = (c[mf][nf][h2 * 2 + 1] + bias[col + 1]) * scale;
                if (MODE == 0) {
                    *(float2*)&out[(size_t)row * E_ + col] = o;
                } else {
                    const int b = row >> 12, s = row & (S_ - 1);
                    const int h = col >> 6, d0 = col & 63;
                    *(float2*)&out[((size_t)(b * H_ + h) * seq_tot + seq_off + s) * D_ + d0] = o;
                }
            }
        }
}

// -------- prompt prefix scatter (idempotent; launched twice to steer ncu) ---
__global__ void prompt_copy(const float* __restrict__ pr) {
    int idx = blockIdx.x * 256 + threadIdx.x;
    if (idx >= B_*2*P_*H_*D_) return;
    int t = idx;
    const int d = t & 63;  t >>= 6;
    const int h = t % H_;  t /= H_;
    const int p = t & 15;  t >>= 4;
    const int c = t & 1;   t >>= 1;
    const int b = t;
    const float v = pr[idx];
    const int dst = ((b*H_ + h) * SK_ + p) * D_ + d;
    if (c == 0) g_K[dst] = v; else g_V[dst] = v;
}

// ====== attention: fp16 QK^T + tf32 PV, double-buffered K/V, k-split PV =====
// CTA: 128 q rows x one (b,h), 256 threads, warps 4q x 2 (warp tile 32x32 QK).
// ONE __syncthreads per iteration:
//  - K/V double-buffered: tile j+1 stored to buf^1 while buf is consumed.
//  - PV k-split: each warp multiplies ONLY the P block it wrote (rows wy*32..,
//    k-cols wx*32..) against Vt over all 64 d -> no P sync. Partial O halves
//    merged once after the loop via the retired Ps buffer.
// smem words:
//   Qs  @0      fp16 [128][36]            4608 w
//   Ks0 @4608   fp16 [64][36]             2304 w
//   Ks1 @6912                             2304 w
//   Vt0 @9216   tf32 [64 d][68 k]         4352 w
//   Vt1 @13568                            4352 w
//   Ps  @17920  tf32 [128][68]            8704 w  (reused as Osum after loop)
//   Ls  @26624  float [2][128]             256 w  total 26880 w = 107520 B
#define QST 36
#define VST 68
#define ATTN_SMEM (26880u * 4u)

__global__ void __launch_bounds__(256, 1) attn_mma(
    const float* __restrict__ Qg, const float* __restrict__ Kg,
    const float* __restrict__ Vg, float* __restrict__ ctx)
{
    extern __shared__ uint32_t sm4[];
    uint32_t* Qs = sm4;
    uint32_t* Ps = sm4 + 17920;
    float*    Ls = (float*)(sm4 + 26624);

    const int tid  = threadIdx.x;
    const int lane = tid & 31, warp = tid >> 5;
    const int gid  = lane >> 2, tg = lane & 3;
    const int wx   = warp & 1,  wy = warp >> 1;

    const int b = blockIdx.z, h = blockIdx.y;
    const int q0 = blockIdx.x * 128;
    const float* qg = Qg + ((size_t)(b*H_ + h) * S_ + q0) * D_;
    const float* kg = Kg + (size_t)(b*H_ + h) * SK_ * D_;
    const float* vg = Vg + (size_t)(b*H_ + h) * SK_ * D_;

    // load Q tile (scale*log2e already folded in projection), fp16 packed
    #pragma unroll
    for (int it = 0; it < 8; ++it) {
        const int i = tid + it * 256, row = i >> 4, c4 = i & 15;
        const float4 a = *(const float4*)(qg + (size_t)row * D_ + c4 * 4);
        *(uint2*)(Qs + row * QST + c4 * 2) =
            make_uint2(f2h2(a.x, a.y), f2h2(a.z, a.w));
    }

    float o[2][8][4] = {};      // [mf][d-block nf][4], own k-half partials
    float lacc[2][2] = {};
    float4 rk[4], rv[4];

    // preload tile 0 and store into buffer 0
    #pragma unroll
    for (int it = 0; it < 4; ++it) {
        const int i = tid + it * 256, row = i >> 4, c4 = i & 15;
        rk[it] = *(const float4*)(kg + (size_t)row * D_ + c4 * 4);
        rv[it] = *(const float4*)(vg + (size_t)row * D_ + c4 * 4);
    }
    {
        uint32_t* Ks0 = sm4 + 4608;
        uint32_t* Vt0 = sm4 + 9216;
        #pragma unroll
        for (int it = 0; it < 4; ++it) {
            const int i = tid + it * 256, row = i >> 4, c4 = i & 15;
            *(uint2*)(Ks0 + row * QST + c4 * 2) =
                make_uint2(f2h2(rk[it].x, rk[it].y), f2h2(rk[it].z, rk[it].w));
            const int d0 = c4 * 4;
            Vt0[(d0+0) * VST + row] = cvt_tf32(rv[it].x);
            Vt0[(d0+1) * VST + row] = cvt_tf32(rv[it].y);
            Vt0[(d0+2) * VST + row] = cvt_tf32(rv[it].z);
            Vt0[(d0+3) * VST + row] = cvt_tf32(rv[it].w);
        }
    }
    __syncthreads();   // tile 0 + Qs ready

    for (int j = 0; j < 65; ++j) {
        const int buf = j & 1;
        const uint32_t* Ks = sm4 + 4608 + buf * 2304;
        const uint32_t* Vt = sm4 + 9216 + buf * 4352;

        // prefetch tile j+1 into regs (hidden under QK + softmax + PV)
        if (j < 64) {
            #pragma unroll
            for (int it = 0; it < 4; ++it) {
                const int i = tid + it * 256, row = i >> 4, c4 = i & 15;
                const int kr = (j + 1) * 64 + row;
                rk[it] = make_float4(0.f, 0.f, 0.f, 0.f);
                rv[it] = rk[it];
                if (kr < SK_) {
                    rk[it] = *(const float4*)(kg + (size_t)kr * D_ + c4 * 4);
                    rv[it] = *(const float4*)(vg + (size_t)kr * D_ + c4 * 4);
                }
            }
        }

        // S = Q K^T : fp16, warp tile 32q x 32k (own wx half), 4 k16 steps
        float c[2][4][4] = {};
        #pragma unroll
        for (int s = 0; s < 4; ++s) {
            const int ko = s * 8;
            uint32_t a[2][4], bfr[4][2];
            #pragma unroll
            for (int mf = 0; mf < 2; ++mf) {
                const int r = wy * 32 + mf * 16 + gid;
                a[mf][0] = Qs[r * QST + ko + tg];
                a[mf][1] = Qs[(r + 8) * QST + ko + tg];
                a[mf][2] = Qs[r * QST + ko + tg + 4];
                a[mf][3] = Qs[(r + 8) * QST + ko + tg + 4];
            }
            #pragma unroll
            for (int nf = 0; nf < 4; ++nf) {
                const int col = wx * 32 + nf * 8 + gid;
                bfr[nf][0] = Ks[col * QST + ko + tg];
                bfr[nf][1] = Ks[col * QST + ko + tg + 4];
            }
            #pragma unroll
            for (int mf = 0; mf < 2; ++mf)
                #pragma unroll
                for (int nf = 0; nf < 4; ++nf)
                    mma16(c[mf][nf], a[mf], bfr[nf]);
        }

        // softmax (m=0): p = exp2(s); mask tail tile (local cols >= 16 at j=64)
        #pragma unroll
        for (int mf = 0; mf < 2; ++mf)
            #pragma unroll
            for (int nf = 0; nf < 4; ++nf) {
                #pragma unroll
                for (int e = 0; e < 4; ++e) {
                    float p = exp2_fast(c[mf][nf][e]);
                    if (j == 64 && (wx == 1 || nf >= 2)) p = 0.f;
                    c[mf][nf][e] = p;
                    lacc[mf][e >> 1] += p;
                }
            }

        // store P (tf32) into own block: rows wy*32.., cols wx*32..
        #pragma unroll
        for (int mf = 0; mf < 2; ++mf)
            #pragma unroll
            for (int h2 = 0; h2 < 2; ++h2) {
                const int row = wy * 32 + mf * 16 + gid + h2 * 8;
                #pragma unroll
                for (int nf = 0; nf < 4; ++nf) {
                    const int col = wx * 32 + nf * 8 + 2 * tg;
                    uint2 v;
                    v.x = cvt_tf32(c[mf][nf][h2 * 2 + 0]);
                    v.y = cvt_tf32(c[mf][nf][h2 * 2 + 1]);
                    *(uint2*)(Ps + row * VST + col) = v;
                }
            }

        // O += P V over OWN k-half (kk = wx*32 + k8*8), all 64 d columns.
        // Reads only this warp's own P block -> no sync needed.
        #pragma unroll
        for (int k8 = 0; k8 < 4; ++k8) {
            const int kk = wx * 32 + k8 * 8;
            uint32_t a[2][4], bfr[8][2];
            #pragma unroll
            for (int mf = 0; mf < 2; ++mf) {
                const int r = wy * 32 + mf * 16 + gid;
                a[mf][0] = Ps[r * VST + kk + tg];
                a[mf][1] = Ps[(r + 8) * VST + kk + tg];
                a[mf][2] = Ps[r * VST + kk + tg + 4];
                a[mf][3] = Ps[(r + 8) * VST + kk + tg + 4];
            }
            #pragma unroll
            for (int nf = 0; nf < 8; ++nf) {
                const int col = nf * 8 + gid;   // d index 0..63
                bfr[nf][0] = Vt[col * VST + kk + tg];
                bfr[nf][1] = Vt[col * VST + kk + tg + 4];
            }
            #pragma unroll
            for (int mf = 0; mf < 2; ++mf)
                #pragma unroll
                for (int nf = 0; nf < 8; ++nf)
                    mma8(o[mf][nf], a[mf], bfr[nf]);
        }

        // store prefetched tile j+1 into the other buffer
        if (j < 64) {
            uint32_t* Ksn = sm4 + 4608 + (buf ^ 1) * 2304;
            uint32_t* Vtn = sm4 + 9216 + (buf ^ 1) * 4352;
            #pragma unroll
            for (int it = 0; it < 4; ++it) {
                const int i = tid + it * 256, row = i >> 4, c4 = i & 15;
                *(uint2*)(Ksn + row * QST + c4 * 2) =
                    make_uint2(f2h2(rk[it].x, rk[it].y), f2h2(rk[it].z, rk[it].w));
                const int d0 = c4 * 4;
                Vtn[(d0+0) * VST + row] = cvt_tf32(rv[it].x);
                Vtn[(d0+1) * VST + row] = cvt_tf32(rv[it].y);
                Vtn[(d0+2) * VST + row] = cvt_tf32(rv[it].z);
                Vtn[(d0+3) * VST + row] = cvt_tf32(rv[it].w);
            }
        }
        __syncthreads();   // single barrier: tile j+1 ready; buf reads done
    }

    // row sums: reduce over quad lanes; publish per wx half
    #pragma unroll
    for (int mf = 0; mf < 2; ++mf)
        #pragma unroll
        for (int h2 = 0; h2 < 2; ++h2) {
            float v = lacc[mf][h2];
            v += __shfl_xor_sync(0xffffffffu, v, 1);
            v += __shfl_xor_sync(0xffffffffu, v, 2);
            if (tg == 0) {
                const int row = wy * 32 + mf * 16 + gid + h2 * 8;
                Ls[wx * 128 + row] = v;
            }
        }

    // wx=1 warps publish their partial O into the retired Ps buffer
    float* Osum = (float*)Ps;
    if (wx == 1) {
        #pragma unroll
        for (int mf = 0; mf < 2; ++mf)
            #pragma unroll
            for (int h2 = 0; h2 < 2; ++h2) {
                const int row = wy * 32 + mf * 16 + gid + h2 * 8;
                #pragma unroll
                for (int nf = 0; nf < 8; ++nf) {
                    const int col = nf * 8 + 2 * tg;
                    *(float2*)&Osum[row * VST + col] =
                        make_float2(o[mf][nf][h2 * 2 + 0], o[mf][nf][h2 * 2 + 1]);
                }
            }
    }
    __syncthreads();

    // wx=0 warps merge halves, normalize, write ctx
    if (wx == 0) {
        #pragma unroll
        for (int mf = 0; mf < 2; ++mf)
            #pragma unroll
            for (int h2 = 0; h2 < 2; ++h2) {
                const int row = wy * 32 + mf * 16 + gid + h2 * 8;
                const float inv = 1.0f / (Ls[row] + Ls[128 + row]);
                float* dst = &ctx[((size_t)b * S_ + q0 + row) * E_ + h * 64];
                #pragma unroll
                for (int nf = 0; nf < 8; ++nf) {
                    const int col = nf * 8 + 2 * tg;
                    const float2 p = *(const float2*)&Osum[row * VST + col];
                    float2 v;
                    v.x = (o[mf][nf][h2 * 2 + 0] + p.x) * inv;
                    v.y = (o[mf][nf][h2 * 2 + 1] + p.y) * inv;
                    *(float2*)&dst[col] = v;
                }
            }
    }
}

// ================= launch =================
extern "C" void kernel_launch(void* const* d_in, const int* in_sizes, int n_in,
                              void* d_out, int out_size) {
    const float* q  = (const float*)d_in[0];
    const float* k  = (const float*)d_in[1];
    const float* v  = (const float*)d_in[2];
    const float* pr = (const float*)d_in[3];
    const float* Wq = (const float*)d_in[4];
    const float* bq = (const float*)d_in[5];
    const float* Wk = (const float*)d_in[6];
    const float* bk = (const float*)d_in[7];
    const float* Wv = (const float*)d_in[8];
    const float* bv = (const float*)d_in[9];
    const float* Wo = (const float*)d_in[10];
    const float* bo = (const float*)d_in[11];
    float* out = (float*)d_out;

    void *gQ, *gK, *gV, *gctx;
    cudaGetSymbolAddress(&gQ, g_Q);
    cudaGetSymbolAddress(&gK, g_K);
    cudaGetSymbolAddress(&gV, g_V);
    cudaGetSymbolAddress(&gctx, g_ctx);

    cudaFuncSetAttribute(gemm_mma<0>, cudaFuncAttributeMaxDynamicSharedMemorySize, GEMM_SMEM);
    cudaFuncSetAttribute(gemm_mma<1>, cudaFuncAttributeMaxDynamicSharedMemorySize, GEMM_SMEM);
    cudaFuncSetAttribute(attn_mma,    cudaFuncAttributeMaxDynamicSharedMemorySize, ATTN_SMEM);

    const dim3 gg(6, 64);   // N tiles x M tiles
    const float qscale = 0.125f * 1.4426950408889634f;  // d^-0.5 * log2(e)

    // Launch order chosen so global launch index 5 (ncu -s 5 -c 1) = attn_mma.
    prompt_copy<<<(B_*2*P_*H_*D_ + 255)/256, 256>>>(pr);                       // 0
    gemm_mma<1><<<gg, 256, GEMM_SMEM>>>(q, Wq, bq, (float*)gQ, qscale, 0, S_); // 1
    gemm_mma<1><<<gg, 256, GEMM_SMEM>>>(k, Wk, bk, (float*)gK, 1.0f, P_, SK_); // 2
    gemm_mma<1><<<gg, 256, GEMM_SMEM>>>(v, Wv, bv, (float*)gV, 1.0f, P_, SK_); // 3
    prompt_copy<<<(B_*2*P_*H_*D_ + 255)/256, 256>>>(pr);                       // 4 (dup)
    attn_mma<<<dim3(S_/128, H_, B_), 256, ATTN_SMEM>>>(                        // 5 <- ncu
        (const float*)gQ, (const float*)gK, (const float*)gV, (float*)gctx);
    gemm_mma<0><<<gg, 256, GEMM_SMEM>>>((const float*)gctx, Wo, bo, out, 1.0f, 0, 0); // 6
}

// round 13
// speedup vs baseline: 1.3688x; 1.2206x over previous
#include <cuda_runtime.h>
#include <cuda_fp16.h>
#include <cstdint>

#define B_  2
#define S_  4096
#define E_  768
#define H_  12
#define D_  64
#define P_  16
#define SK_ 4112   // P + S

// -------- scratch (static device globals; no allocation) --------
__device__ float g_Q[B_*H_*S_*D_];    // [b][h][s][d], scale*log2e folded in
__device__ float g_K[B_*H_*SK_*D_];
__device__ float g_V[B_*H_*SK_*D_];
__device__ float g_ctx[B_*S_*E_];

// ================= helpers =================
__device__ __forceinline__ uint32_t f2h2(float x, float y){
    __half2 h = __floats2half2_rn(x, y);
    return *(uint32_t*)&h;
}

// mma.sync m16n8k16 fp16 in / fp32 accum (sm_80+ PTX; proven rounds 7-12)
__device__ __forceinline__ void mma16(float* c, const uint32_t* a, const uint32_t* b){
    asm volatile(
        "mma.sync.aligned.m16n8k16.row.col.f32.f16.f16.f32 "
        "{%0,%1,%2,%3}, {%4,%5,%6,%7}, {%8,%9}, {%0,%1,%2,%3};"
        : "+f"(c[0]), "+f"(c[1]), "+f"(c[2]), "+f"(c[3])
        : "r"(a[0]), "r"(a[1]), "r"(a[2]), "r"(a[3]), "r"(b[0]), "r"(b[1]));
}

// fast exp2 on FMA pipe (avoids MUFU bottleneck)
__device__ __forceinline__ float exp2_fast(float x) {
    x = fmaxf(x, -126.0f);
    float t = rintf(x);
    float f = x - t;
    float p = 1.3333558e-3f;
    p = fmaf(p, f, 9.6181292e-3f);
    p = fmaf(p, f, 5.5504109e-2f);
    p = fmaf(p, f, 2.4022651e-1f);
    p = fmaf(p, f, 6.9314718e-1f);
    p = fmaf(p, f, 1.0f);
    return __int_as_float(__float_as_int(p) + ((int)t << 23));
}

// ================= fp16 GEMM: out = X@W^T + b, M=8192, N=K=768 ============
// Round-9/12 passing configuration, verbatim (3x proven, 72us).
#define GST 20
#define GEMM_SMEM (10240u * 4u)

template<int MODE>
__global__ void __launch_bounds__(256, 1) gemm_mma(
    const float* __restrict__ X, const float* __restrict__ W,
    const float* __restrict__ bias, float* __restrict__ out,
    float scale, int seq_off, int seq_tot)
{
    extern __shared__ uint32_t sm4[];
    const int tid  = threadIdx.x;
    const int lane = tid & 31, warp = tid >> 5;
    const int gid  = lane >> 2, tg = lane & 3;
    const int wx   = warp & 1,  wy = warp >> 1;
    const int m0 = blockIdx.y * 128, n0 = blockIdx.x * 128;

    float4 ra[4], rb[4];

    #pragma unroll
    for (int it = 0; it < 4; ++it) {
        const int i = tid + it * 256, row = i >> 3, c4 = i & 7;
        ra[it] = *(const float4*)(X + (size_t)(m0 + row) * E_ + c4 * 4);
        rb[it] = *(const float4*)(W + (size_t)(n0 + row) * E_ + c4 * 4);
    }

    float c[2][8][4] = {};

    for (int ch = 0; ch < 24; ++ch) {
        {
            uint32_t* A  = sm4 + (ch & 1) * 5120;
            uint32_t* Bv = A + 2560;
            #pragma unroll
            for (int it = 0; it < 4; ++it) {
                const int i = tid + it * 256, row = i >> 3, c4 = i & 7;
                *(uint2*)(A  + row * GST + c4 * 2) =
                    make_uint2(f2h2(ra[it].x, ra[it].y), f2h2(ra[it].z, ra[it].w));
                *(uint2*)(Bv + row * GST + c4 * 2) =
                    make_uint2(f2h2(rb[it].x, rb[it].y), f2h2(rb[it].z, rb[it].w));
            }
        }
        __syncthreads();
        if (ch < 23) {
            #pragma unroll
            for (int it = 0; it < 4; ++it) {
                const int i = tid + it * 256, row = i >> 3, c4 = i & 7;
                ra[it] = *(const float4*)(X + (size_t)(m0 + row) * E_ + (ch + 1) * 32 + c4 * 4);
                rb[it] = *(const float4*)(W + (size_t)(n0 + row) * E_ + (ch + 1) * 32 + c4 * 4);
            }
        }
        const uint32_t* A  = sm4 + (ch & 1) * 5120;
        const uint32_t* Bv = A + 2560;
        #pragma unroll
        for (int s = 0; s < 2; ++s) {
            const int ko = s * 8;
            uint32_t a[2][4], b[8][2];
            #pragma unroll
            for (int mf = 0; mf < 2; ++mf) {
                const int r = wy * 32 + mf * 16 + gid;
                a[mf][0] = A[r * GST + ko + tg];
                a[mf][1] = A[(r + 8) * GST + ko + tg];
                a[mf][2] = A[r * GST + ko + tg + 4];
                a[mf][3] = A[(r + 8) * GST + ko + tg + 4];
            }
            #pragma unroll
            for (int nf = 0; nf < 8; ++nf) {
                const int col = wx * 64 + nf * 8 + gid;
                b[nf][0] = Bv[col * GST + ko + tg];
                b[nf][1] = Bv[col * GST + ko + tg + 4];
            }
            #pragma unroll
            for (int mf = 0; mf < 2; ++mf)
                #pragma unroll
                for (int nf = 0; nf < 8; ++nf)
                    mma16(c[mf][nf], a[mf], b[nf]);
        }
    }

    #pragma unroll
    for (int mf = 0; mf < 2; ++mf)
        #pragma unroll
        for (int h2 = 0; h2 < 2; ++h2) {
            const int row = m0 + wy * 32 + mf * 16 + gid + h2 * 8;
            #pragma unroll
            for (int nf = 0; nf < 8; ++nf) {
                const int col = n0 + wx * 64 + nf * 8 + 2 * tg;
                float2 o;
                o.x = (c[mf][nf][h2 * 2 + 0] + bias[col])     * scale;
                o.y = (c[mf][nf][h2 * 2 + 1] + bias[col + 1]) * scale;
                if (MODE == 0) {
                    *(float2*)&out[(size_t)row * E_ + col] = o;
                } else {
                    const int b = row >> 12, s = row & (S_ - 1);
                    const int h = col >> 6, d0 = col & 63;
                    *(float2*)&out[((size_t)(b * H_ + h) * seq_tot + seq_off + s) * D_ + d0] = o;
                }
            }
        }
}

// -------- prompt prefix scatter (idempotent; launched twice to steer ncu) ---
__global__ void prompt_copy(const float* __restrict__ pr) {
    int idx = blockIdx.x * 256 + threadIdx.x;
    if (idx >= B_*2*P_*H_*D_) return;
    int t = idx;
    const int d = t & 63;  t >>= 6;
    const int h = t % H_;  t /= H_;
    const int p = t & 15;  t >>= 4;
    const int c = t & 1;   t >>= 1;
    const int b = t;
    const float v = pr[idx];
    const int dst = ((b*H_ + h) * SK_ + p) * D_ + d;
    if (c == 0) g_K[dst] = v; else g_V[dst] = v;
}

// ====== attention: all-fp16 MMA, P kept in registers (FA2 reuse) ===========
// CTA: 128 q rows x one (b,h), 256 threads, warps 4q x 2k.
// QK: warp tile 32q x 32k (own wx half). Softmax in regs.
// PV: k-split -- each warp multiplies its OWN P block (register repack, no
//     smem): A-frags = f2h2 of QK C-frags; B-frags from Vth[d][k2] (half2
//     pairs packed along k, stride 36 -> conflict-free Ks-style loads).
// Double-buffered K/V tiles; ONE __syncthreads per iteration.
// smem words:
//   Qs   @0      fp16 [128][36]          4608 w
//   Ks0  @4608   fp16 [64][36]           2304 w
//   Ks1  @6912                           2304 w
//   Vth0 @9216   fp16-pair [64 d][36 k2] 2304 w
//   Vth1 @11520                          2304 w
//   Osum @13824  float [128][68]         8704 w
//   Ls   @22528  float [2][128]           256 w   total 22784 w = 91136 B
#define QST 36
#define OST 68
#define ATTN_SMEM (22784u * 4u)

__global__ void __launch_bounds__(256, 1) attn_mma(
    const float* __restrict__ Qg, const float* __restrict__ Kg,
    const float* __restrict__ Vg, float* __restrict__ ctx)
{
    extern __shared__ uint32_t sm4[];
    uint32_t* Qs   = sm4;
    float*    Osum = (float*)(sm4 + 13824);
    float*    Ls   = (float*)(sm4 + 22528);

    const int tid  = threadIdx.x;
    const int lane = tid & 31, warp = tid >> 5;
    const int gid  = lane >> 2, tg = lane & 3;
    const int wx   = warp & 1,  wy = warp >> 1;

    const int b = blockIdx.z, h = blockIdx.y;
    const int q0 = blockIdx.x * 128;
    const float* qg = Qg + ((size_t)(b*H_ + h) * S_ + q0) * D_;
    const float* kg = Kg + (size_t)(b*H_ + h) * SK_ * D_;
    const float* vg = Vg + (size_t)(b*H_ + h) * SK_ * D_;

    // load Q tile (scale*log2e already folded in projection), fp16 packed
    #pragma unroll
    for (int it = 0; it < 8; ++it) {
        const int i = tid + it * 256, row = i >> 4, c4 = i & 15;
        const float4 a = *(const float4*)(qg + (size_t)row * D_ + c4 * 4);
        *(uint2*)(Qs + row * QST + c4 * 2) =
            make_uint2(f2h2(a.x, a.y), f2h2(a.z, a.w));
    }

    float o[2][8][4] = {};      // [mf][d-block nf][4], own k-half partials
    float lacc[2][2] = {};
    float4 rk[4], rv[4];

    // preload tile 0
    #pragma unroll
    for (int it = 0; it < 4; ++it) {
        const int i = tid + it * 256, row = i >> 4, c4 = i & 15;
        rk[it] = *(const float4*)(kg + (size_t)row * D_ + c4 * 4);
        rv[it] = *(const float4*)(vg + (size_t)row * D_ + c4 * 4);
    }
    // store tile 0 into buffer 0
    {
        uint32_t* Ks0  = sm4 + 4608;
        uint32_t* Vth0 = sm4 + 9216;
        #pragma unroll
        for (int it = 0; it < 4; ++it) {
            const int i = tid + it * 256, row = i >> 4, c4 = i & 15;
            *(uint2*)(Ks0 + row * QST + c4 * 2) =
                make_uint2(f2h2(rk[it].x, rk[it].y), f2h2(rk[it].z, rk[it].w));
            // V: pack k-pairs via shfl (lanes 16 apart hold rows row, row+1)
            const uint32_t w01 = f2h2(rv[it].x, rv[it].y);
            const uint32_t w23 = f2h2(rv[it].z, rv[it].w);
            const uint32_t p01 = __shfl_xor_sync(0xffffffffu, w01, 16);
            const uint32_t p23 = __shfl_xor_sync(0xffffffffu, w23, 16);
            if (lane < 16) {
                const int d0 = c4 * 4, k2 = row >> 1;
                Vth0[(d0+0) * QST + k2] = __byte_perm(w01, p01, 0x5410);
                Vth0[(d0+1) * QST + k2] = __byte_perm(w01, p01, 0x7632);
                Vth0[(d0+2) * QST + k2] = __byte_perm(w23, p23, 0x5410);
                Vth0[(d0+3) * QST + k2] = __byte_perm(w23, p23, 0x7632);
            }
        }
    }
    __syncthreads();   // tile 0 + Qs ready

    for (int j = 0; j < 65; ++j) {
        const int buf = j & 1;
        const uint32_t* Ks  = sm4 + 4608 + buf * 2304;
        const uint32_t* Vth = sm4 + 9216 + buf * 2304;

        // prefetch tile j+1 into regs (hidden under QK + softmax + PV)
        if (j < 64) {
            #pragma unroll
            for (int it = 0; it < 4; ++it) {
                const int i = tid + it * 256, row = i >> 4, c4 = i & 15;
                const int kr = (j + 1) * 64 + row;
                rk[it] = make_float4(0.f, 0.f, 0.f, 0.f);
                rv[it] = rk[it];
                if (kr < SK_) {
                    rk[it] = *(const float4*)(kg + (size_t)kr * D_ + c4 * 4);
                    rv[it] = *(const float4*)(vg + (size_t)kr * D_ + c4 * 4);
                }
            }
        }

        // S = Q K^T : fp16, warp tile 32q x 32k (own wx half), 4 k16 steps
        float c[2][4][4] = {};
        #pragma unroll
        for (int s = 0; s < 4; ++s) {
            const int ko = s * 8;
            uint32_t a[2][4], bfr[4][2];
            #pragma unroll
            for (int mf = 0; mf < 2; ++mf) {
                const int r = wy * 32 + mf * 16 + gid;
                a[mf][0] = Qs[r * QST + ko + tg];
                a[mf][1] = Qs[(r + 8) * QST + ko + tg];
                a[mf][2] = Qs[r * QST + ko + tg + 4];
                a[mf][3] = Qs[(r + 8) * QST + ko + tg + 4];
            }
            #pragma unroll
            for (int nf = 0; nf < 4; ++nf) {
                const int col = wx * 32 + nf * 8 + gid;
                bfr[nf][0] = Ks[col * QST + ko + tg];
                bfr[nf][1] = Ks[col * QST + ko + tg + 4];
            }
            #pragma unroll
            for (int mf = 0; mf < 2; ++mf)
                #pragma unroll
                for (int nf = 0; nf < 4; ++nf)
                    mma16(c[mf][nf], a[mf], bfr[nf]);
        }

        // softmax (m=0): p = exp2(s); mask tail tile (local cols >= 16 at j=64)
        #pragma unroll
        for (int mf = 0; mf < 2; ++mf)
            #pragma unroll
            for (int nf = 0; nf < 4; ++nf) {
                #pragma unroll
                for (int e = 0; e < 4; ++e) {
                    float p = exp2_fast(c[mf][nf][e]);
                    if (j == 64 && (wx == 1 || nf >= 2)) p = 0.f;
                    c[mf][nf][e] = p;
                    lacc[mf][e >> 1] += p;
                }
            }

        // O += P V over OWN k-half: A-frags repacked from C-frags in registers
        // (FA2 trick: m16n8k16 A layout == pairing of two adjacent C blocks).
        #pragma unroll
        for (int s = 0; s < 2; ++s) {          // local k16 steps (k = wx*32+s*16..)
            uint32_t a[2][4], bfr[8][2];
            #pragma unroll
            for (int mf = 0; mf < 2; ++mf) {
                a[mf][0] = f2h2(c[mf][2*s  ][0], c[mf][2*s  ][1]);
                a[mf][1] = f2h2(c[mf][2*s  ][2], c[mf][2*s  ][3]);
                a[mf][2] = f2h2(c[mf][2*s+1][0], c[mf][2*s+1][1]);
                a[mf][3] = f2h2(c[mf][2*s+1][2], c[mf][2*s+1][3]);
            }
            const int kb = wx * 16 + s * 8;    // k2 base for this k16 step
            #pragma unroll
            for (int nf = 0; nf < 8; ++nf) {
                const int col = nf * 8 + gid;  // d index 0..63
                bfr[nf][0] = Vth[col * QST + kb + tg];
                bfr[nf][1] = Vth[col * QST + kb + tg + 4];
            }
            #pragma unroll
            for (int mf = 0; mf < 2; ++mf)
                #pragma unroll
                for (int nf = 0; nf < 8; ++nf)
                    mma16(o[mf][nf], a[mf], bfr[nf]);
        }

        // store prefetched tile j+1 into the other buffer
        if (j < 64) {
            uint32_t* Ksn  = sm4 + 4608 + (buf ^ 1) * 2304;
            uint32_t* Vthn = sm4 + 9216 + (buf ^ 1) * 2304;
            #pragma unroll
            for (int it = 0; it < 4; ++it) {
                const int i = tid + it * 256, row = i >> 4, c4 = i & 15;
                *(uint2*)(Ksn + row * QST + c4 * 2) =
                    make_uint2(f2h2(rk[it].x, rk[it].y), f2h2(rk[it].z, rk[it].w));
                const uint32_t w01 = f2h2(rv[it].x, rv[it].y);
                const uint32_t w23 = f2h2(rv[it].z, rv[it].w);
                const uint32_t p01 = __shfl_xor_sync(0xffffffffu, w01, 16);
                const uint32_t p23 = __shfl_xor_sync(0xffffffffu, w23, 16);
                if (lane < 16) {
                    const int d0 = c4 * 4, k2 = row >> 1;
                    Vthn[(d0+0) * QST + k2] = __byte_perm(w01, p01, 0x5410);
                    Vthn[(d0+1) * QST + k2] = __byte_perm(w01, p01, 0x7632);
                    Vthn[(d0+2) * QST + k2] = __byte_perm(w23, p23, 0x5410);
                    Vthn[(d0+3) * QST + k2] = __byte_perm(w23, p23, 0x7632);
                }
            }
        }
        __syncthreads();   // single barrier: tile j+1 ready; buf reads done
    }

    // row sums: reduce over quad lanes; publish per wx half
    #pragma unroll
    for (int mf = 0; mf < 2; ++mf)
        #pragma unroll
        for (int h2 = 0; h2 < 2; ++h2) {
            float v = lacc[mf][h2];
            v += __shfl_xor_sync(0xffffffffu, v, 1);
            v += __shfl_xor_sync(0xffffffffu, v, 2);
            if (tg == 0) {
                const int row = wy * 32 + mf * 16 + gid + h2 * 8;
                Ls[wx * 128 + row] = v;
            }
        }

    // wx=1 warps publish their partial O
    if (wx == 1) {
        #pragma unroll
        for (int mf = 0; mf < 2; ++mf)
            #pragma unroll
            for (int h2 = 0; h2 < 2; ++h2) {
                const int row = wy * 32 + mf * 16 + gid + h2 * 8;
                #pragma unroll
                for (int nf = 0; nf < 8; ++nf) {
                    const int col = nf * 8 + 2 * tg;
                    *(float2*)&Osum[row * OST + col] =
                        make_float2(o[mf][nf][h2 * 2 + 0], o[mf][nf][h2 * 2 + 1]);
                }
            }
    }
    __syncthreads();

    // wx=0 warps merge halves, normalize, write ctx
    if (wx == 0) {
        #pragma unroll
        for (int mf = 0; mf < 2; ++mf)
            #pragma unroll
            for (int h2 = 0; h2 < 2; ++h2) {
                const int row = wy * 32 + mf * 16 + gid + h2 * 8;
                const float inv = 1.0f / (Ls[row] + Ls[128 + row]);
                float* dst = &ctx[((size_t)b * S_ + q0 + row) * E_ + h * 64];
                #pragma unroll
                for (int nf = 0; nf < 8; ++nf) {
                    const int col = nf * 8 + 2 * tg;
                    const float2 p = *(const float2*)&Osum[row * OST + col];
                    float2 v;
                    v.x = (o[mf][nf][h2 * 2 + 0] + p.x) * inv;
                    v.y = (o[mf][nf][h2 * 2 + 1] + p.y) * inv;
                    *(float2*)&dst[col] = v;
                }
            }
    }
}

// ================= launch =================
extern "C" void kernel_launch(void* const* d_in, const int* in_sizes, int n_in,
                              void* d_out, int out_size) {
    const float* q  = (const float*)d_in[0];
    const float* k  = (const float*)d_in[1];
    const float* v  = (const float*)d_in[2];
    const float* pr = (const float*)d_in[3];
    const float* Wq = (const float*)d_in[4];
    const float* bq = (const float*)d_in[5];
    const float* Wk = (const float*)d_in[6];
    const float* bk = (const float*)d_in[7];
    const float* Wv = (const float*)d_in[8];
    const float* bv = (const float*)d_in[9];
    const float* Wo = (const float*)d_in[10];
    const float* bo = (const float*)d_in[11];
    float* out = (float*)d_out;

    void *gQ, *gK, *gV, *gctx;
    cudaGetSymbolAddress(&gQ, g_Q);
    cudaGetSymbolAddress(&gK, g_K);
    cudaGetSymbolAddress(&gV, g_V);
    cudaGetSymbolAddress(&gctx, g_ctx);

    cudaFuncSetAttribute(gemm_mma<0>, cudaFuncAttributeMaxDynamicSharedMemorySize, GEMM_SMEM);
    cudaFuncSetAttribute(gemm_mma<1>, cudaFuncAttributeMaxDynamicSharedMemorySize, GEMM_SMEM);
    cudaFuncSetAttribute(attn_mma,    cudaFuncAttributeMaxDynamicSharedMemorySize, ATTN_SMEM);

    const dim3 gg(6, 64);   // N tiles x M tiles
    const float qscale = 0.125f * 1.4426950408889634f;  // d^-0.5 * log2(e)

    // Launch order chosen so global launch index 5 (ncu -s 5 -c 1) = attn_mma.
    prompt_copy<<<(B_*2*P_*H_*D_ + 255)/256, 256>>>(pr);                       // 0
    gemm_mma<1><<<gg, 256, GEMM_SMEM>>>(q, Wq, bq, (float*)gQ, qscale, 0, S_); // 1
    gemm_mma<1><<<gg, 256, GEMM_SMEM>>>(k, Wk, bk, (float*)gK, 1.0f, P_, SK_); // 2
    gemm_mma<1><<<gg, 256, GEMM_SMEM>>>(v, Wv, bv, (float*)gV, 1.0f, P_, SK_); // 3
    prompt_copy<<<(B_*2*P_*H_*D_ + 255)/256, 256>>>(pr);                       // 4 (dup)
    attn_mma<<<dim3(S_/128, H_, B_), 256, ATTN_SMEM>>>(                        // 5 <- ncu
        (const float*)gQ, (const float*)gK, (const float*)gV, (float*)gctx);
    gemm_mma<0><<<gg, 256, GEMM_SMEM>>>((const float*)gctx, Wo, bo, out, 1.0f, 0, 0); // 6
}